// round 5
// baseline (speedup 1.0000x reference)
#include <cuda_runtime.h>
#include <float.h>

// Density_loss: mean-of-16-NN-squared-distances per point, averaged per cloud,
// then MSE between seed and gt clouds over batch. B=8, N=2048, C=3, K=16.

#define NPTS  2048
#define BLK   256
#define TILES (NPTS / BLK)   // 8
#define BATCH 8
#define KNN   16

// Per-block partial sums: [which(2)][batch(8)][tile(8)] — written (not
// accumulated) every launch, so no zeroing kernel needed. Deterministic.
__device__ float g_partials[2 * BATCH * TILES];

__global__ __launch_bounds__(BLK, 1)
void knn_tile_kernel(const float* __restrict__ seed,
                     const float* __restrict__ gt) {
    __shared__ float4 sp[NPTS];          // 32 KB: all points of this batch
    __shared__ float  sred[BLK / 32];

    const int tile  = blockIdx.x;
    const int b     = blockIdx.y;
    const int which = blockIdx.z;

    const float* __restrict__ pts =
        (which == 0 ? seed : gt) + (size_t)b * NPTS * 3;

    // Stage all 2048 points into SMEM as float4 (w unused).
    for (int i = threadIdx.x; i < NPTS; i += BLK) {
        const float* p = pts + 3 * i;
        sp[i] = make_float4(p[0], p[1], p[2], 0.0f);
    }
    __syncthreads();

    const int qi = tile * BLK + threadIdx.x;
    const float qx = sp[qi].x, qy = sp[qi].y, qz = sp[qi].z;

    // Sorted ascending list of the 16 smallest distances (registers only —
    // every index is a compile-time constant after unrolling).
    float best[KNN];
#pragma unroll
    for (int k = 0; k < KNN; ++k) best[k] = FLT_MAX;
    float thresh = FLT_MAX;  // == best[15]

#pragma unroll 4
    for (int j = 0; j < NPTS; ++j) {
        const float4 p = sp[j];
        const float dx = qx - p.x;
        const float dy = qy - p.y;
        const float dz = qz - p.z;
        const float d  = fmaf(dx, dx, fmaf(dy, dy, dz * dz));
        if (d < thresh) {
            // Insert d into sorted position via min/max carry chain; the
            // previous maximum falls off the end.
            float v = d;
#pragma unroll
            for (int k = 0; k < KNN; ++k) {
                const float lo = fminf(best[k], v);
                v       = fmaxf(best[k], v);
                best[k] = lo;
            }
            thresh = best[KNN - 1];
        }
    }

    // Per-point mean of the 16 nearest squared distances.
    float s = 0.0f;
#pragma unroll
    for (int k = 0; k < KNN; ++k) s += best[k];
    s *= (1.0f / KNN);

    // Deterministic block reduction: warp shuffle tree, then warp leaders.
#pragma unroll
    for (int off = 16; off > 0; off >>= 1)
        s += __shfl_down_sync(0xffffffffu, s, off);
    if ((threadIdx.x & 31) == 0) sred[threadIdx.x >> 5] = s;
    __syncthreads();
    if (threadIdx.x == 0) {
        float t = 0.0f;
#pragma unroll
        for (int w = 0; w < BLK / 32; ++w) t += sred[w];
        g_partials[(which * BATCH + b) * TILES + tile] = t;
    }
}

__global__ void finalize_kernel(float* __restrict__ out) {
    const int lane = threadIdx.x;   // launched with 32 threads
    float s = 0.0f;
    if (lane < 2 * BATCH) {
        const int base = lane * TILES;     // lane = which*8 + b
#pragma unroll
        for (int t = 0; t < TILES; ++t) s += g_partials[base + t];
        s *= (1.0f / NPTS);                // dis[b] (lane<8: seed, 8..15: gt)
    }
    const float other = __shfl_xor_sync(0xffffffffu, s, 8); // pair seed<->gt
    float diff = s - other;
    float d2   = diff * diff;
    if (lane >= 8) d2 = 0.0f;   // count each batch element once (lanes 0..7)
#pragma unroll
    for (int off = 4; off > 0; off >>= 1)
        d2 += __shfl_down_sync(0xffffffffu, d2, off);
    if (lane == 0) out[0] = d2 * (1.0f / BATCH);
}

extern "C" void kernel_launch(void* const* d_in, const int* in_sizes, int n_in,
                              void* d_out, int out_size) {
    const float* seed = (const float*)d_in[0];
    const float* gt_s = (const float*)d_in[1];
    float* out = (float*)d_out;

    dim3 grid(TILES, BATCH, 2);
    knn_tile_kernel<<<grid, BLK>>>(seed, gt_s);
    finalize_kernel<<<1, 32>>>(out);
}